// round 16
// baseline (speedup 1.0000x reference)
#include <cuda_runtime.h>
#include <cuda_bf16.h>
#include <cstdint>

// Problem constants
#define NROWS   200000
#define FEAT    256
#define NCLASS  1000
#define NIMG    64
#define KPI     100
#define SLOTS   512            // padded rows-per-class capacity (max actual ~270)
#define CPAD    32             // cursor padding: 1 counter per 128B L2 line
#define COOC_RPB 4
#define COOC_CTAS   (NCLASS / COOC_RPB)          // 250
#define SCAT_CTAS   ((NROWS/2 + 255) / 256)      // 391
#define K1_GRID     (COOC_CTAS + SCAT_CTAS)      // 641 -> single wave

// Accum decomposition: split NSPLIT classes into 2 half-CTAs each so the
// grid holds exactly one full register-limited wave of warps.
//   816 single-class CTAs + 184*2 half-CTAs = 1184 = 148 SMs x 8 CTAs.
#define NSPLIT    184
#define N_SINGLE  (NCLASS - NSPLIT)              // 816
#define ACC_GRID  (N_SINGLE + 2 * NSPLIT)        // 1184

// Output layout (float32): [protos 256000][init 1000][cooc 1000000]
#define OUT_PROTO 0
#define OUT_INIT  (NCLASS*FEAT)
#define OUT_COOC  (NCLASS*FEAT + NCLASS)

// ---------------- device scratch (no allocation allowed) ----------------
// Invariants at kernel_launch entry: g_cursor_pad == 0, g_flag == 0,
// g_partial == 0. Zero-init covers call #1; the accum kernel restores all
// three every run (single CTAs: cursor; split finisher: flag+partial+cursor).
__device__ int   g_cursor_pad[NCLASS * CPAD];
__device__ int   g_rowidx[NCLASS * SLOTS];
__device__ float g_partial[NSPLIT * FEAT];
__device__ int   g_flag[NSPLIT];

// ---------------- K1: grid-specialized cooc | scatter ---------------------
// R11 verbatim — best measured k1. Scatter's ~8us is a per-LTS-slice
// atomic-throughput floor; every alternative tried (ILP, occupancy,
// counter splits, smem aggregation) lost to this version.
__global__ void __launch_bounds__(256)
k_cooc_scatter(const int* __restrict__ labels,
               const int* __restrict__ lpi,
               const float* __restrict__ cooc_in,
               float* __restrict__ out)
{
    int t   = threadIdx.x;
    int bid = blockIdx.x;

    if (bid >= COOC_CTAS) {
        // ---- scatter role: one int2 label pair per thread ----
        int i = (bid - COOC_CTAS) * 256 + t;
        if (i < NROWS / 2) {
            int2 l = __ldg(reinterpret_cast<const int2*>(labels) + i);
            int p0 = atomicAdd(&g_cursor_pad[l.x * CPAD], 1);
            int p1 = atomicAdd(&g_cursor_pad[l.y * CPAD], 1);
            int r = 2 * i;
            if (p0 < SLOTS) g_rowidx[l.x * SLOTS + p0] = r + 0;
            if (p1 < SLOTS) g_rowidx[l.y * SLOTS + p1] = r + 1;
        }
        return;
    }

    // ---- cooc role ----
    __shared__ unsigned long long scol[NCLASS];
    for (int k = t; k < NCLASS; k += 256) scol[k] = 0ULL;
    __syncthreads();
    for (int k = t; k < NIMG * KPI; k += 256) {
        int img = k / KPI;
        atomicOr(&scol[__ldg(&lpi[k])], 1ULL << img);
    }
    __syncthreads();

    int i0 = bid * COOC_RPB;
    if (t < NCLASS / 4) {
        int j0 = t * 4;
        unsigned long long c0 = scol[j0 + 0];
        unsigned long long c1 = scol[j0 + 1];
        unsigned long long c2 = scol[j0 + 2];
        unsigned long long c3 = scol[j0 + 3];
        #pragma unroll
        for (int rr = 0; rr < COOC_RPB; ++rr) {
            int i = i0 + rr;
            unsigned long long bi = scol[i];
            const float4* in4 = reinterpret_cast<const float4*>(cooc_in + (size_t)i * NCLASS) + t;
            float4 v = __ldg(in4);
            v.x += (i == j0 + 0) ? 0.f : (float)__popcll(bi & c0);
            v.y += (i == j0 + 1) ? 0.f : (float)__popcll(bi & c1);
            v.z += (i == j0 + 2) ? 0.f : (float)__popcll(bi & c2);
            v.w += (i == j0 + 3) ? 0.f : (float)__popcll(bi & c3);
            reinterpret_cast<float4*>(out + OUT_COOC + (size_t)i * NCLASS)[t] = v;
        }
    }
}

// ---------------- K2: class accumulation, RF-exact single wave ------------
// bids [0,816):     single CTA per class c = NSPLIT + bid, row stride 4.
// bids [816,1184):  half-CTAs; pair (2k,2k+1) covers class k, each half
//                   takes row offsets half*4+warp with stride 8; partial
//                   sums merge via g_partial atomics + arrival flag, and
//                   the SECOND finisher applies the EMA.
// 1184 CTAs x 4 warps = 4736 warps = the 64-reg RF cap (32 warps/SM),
// vs 4000 in all prior configs — R12's warp-BW law predicts DRAM% rises.
__global__ void __launch_bounds__(128, 8)
k_class_accum(const float* __restrict__ features,
              const float* __restrict__ prototypes,
              const int*   __restrict__ init_mask,
              const int*   __restrict__ step_ptr,
              float*       __restrict__ out)
{
    int tid  = threadIdx.x;
    int warp = tid >> 5;       // 0..3
    int lane = tid & 31;
    int bid  = blockIdx.x;

    int c, off, stride;
    bool split;
    int sidx = 0;              // split-class index
    if (bid < N_SINGLE) {
        c = NSPLIT + bid;  off = warp;  stride = 4;  split = false;
    } else {
        int idx = bid - N_SINGLE;
        sidx = idx >> 1;
        int half = idx & 1;
        c = sidx;  off = half * 4 + warp;  stride = 8;  split = true;
    }

    int count = min(g_cursor_pad[c * CPAD], SLOTS);
    const int* __restrict__ rows = &g_rowidx[c * SLOTS];

    float acc[8];
    #pragma unroll
    for (int j = 0; j < 8; ++j) acc[j] = 0.f;

    int r = off;
    while (r + 3 * stride < count) {
        int row0 = __ldg(&rows[r]);
        int row1 = __ldg(&rows[r + stride]);
        int row2 = __ldg(&rows[r + 2 * stride]);
        int row3 = __ldg(&rows[r + 3 * stride]);
        const float4* rp0 = reinterpret_cast<const float4*>(features + (size_t)row0 * FEAT);
        const float4* rp1 = reinterpret_cast<const float4*>(features + (size_t)row1 * FEAT);
        const float4* rp2 = reinterpret_cast<const float4*>(features + (size_t)row2 * FEAT);
        const float4* rp3 = reinterpret_cast<const float4*>(features + (size_t)row3 * FEAT);
        float4 a0 = __ldg(&rp0[lane * 2 + 0]);
        float4 b0 = __ldg(&rp0[lane * 2 + 1]);
        float4 a1 = __ldg(&rp1[lane * 2 + 0]);
        float4 b1 = __ldg(&rp1[lane * 2 + 1]);
        float4 a2 = __ldg(&rp2[lane * 2 + 0]);
        float4 b2 = __ldg(&rp2[lane * 2 + 1]);
        float4 a3 = __ldg(&rp3[lane * 2 + 0]);
        float4 b3 = __ldg(&rp3[lane * 2 + 1]);

        float s0 = a0.x*a0.x + a0.y*a0.y + a0.z*a0.z + a0.w*a0.w
                 + b0.x*b0.x + b0.y*b0.y + b0.z*b0.z + b0.w*b0.w;
        float s1 = a1.x*a1.x + a1.y*a1.y + a1.z*a1.z + a1.w*a1.w
                 + b1.x*b1.x + b1.y*b1.y + b1.z*b1.z + b1.w*b1.w;
        float s2 = a2.x*a2.x + a2.y*a2.y + a2.z*a2.z + a2.w*a2.w
                 + b2.x*b2.x + b2.y*b2.y + b2.z*b2.z + b2.w*b2.w;
        float s3 = a3.x*a3.x + a3.y*a3.y + a3.z*a3.z + a3.w*a3.w
                 + b3.x*b3.x + b3.y*b3.y + b3.z*b3.z + b3.w*b3.w;
        #pragma unroll
        for (int o = 16; o > 0; o >>= 1) {
            s0 += __shfl_xor_sync(0xffffffffu, s0, o);
            s1 += __shfl_xor_sync(0xffffffffu, s1, o);
            s2 += __shfl_xor_sync(0xffffffffu, s2, o);
            s3 += __shfl_xor_sync(0xffffffffu, s3, o);
        }
        float i0 = 1.0f / fmaxf(sqrtf(s0), 1e-12f);
        float i1 = 1.0f / fmaxf(sqrtf(s1), 1e-12f);
        float i2 = 1.0f / fmaxf(sqrtf(s2), 1e-12f);
        float i3 = 1.0f / fmaxf(sqrtf(s3), 1e-12f);
        acc[0] += a0.x*i0 + a1.x*i1 + a2.x*i2 + a3.x*i3;
        acc[1] += a0.y*i0 + a1.y*i1 + a2.y*i2 + a3.y*i3;
        acc[2] += a0.z*i0 + a1.z*i1 + a2.z*i2 + a3.z*i3;
        acc[3] += a0.w*i0 + a1.w*i1 + a2.w*i2 + a3.w*i3;
        acc[4] += b0.x*i0 + b1.x*i1 + b2.x*i2 + b3.x*i3;
        acc[5] += b0.y*i0 + b1.y*i1 + b2.y*i2 + b3.y*i3;
        acc[6] += b0.z*i0 + b1.z*i1 + b2.z*i2 + b3.z*i3;
        acc[7] += b0.w*i0 + b1.w*i1 + b2.w*i2 + b3.w*i3;
        r += 4 * stride;
    }
    while (r < count) {
        int row = __ldg(&rows[r]);
        const float4* rp = reinterpret_cast<const float4*>(features + (size_t)row * FEAT);
        float4 a = __ldg(&rp[lane * 2 + 0]);
        float4 b = __ldg(&rp[lane * 2 + 1]);
        float s = a.x*a.x + a.y*a.y + a.z*a.z + a.w*a.w
                + b.x*b.x + b.y*b.y + b.z*b.z + b.w*b.w;
        #pragma unroll
        for (int o = 16; o > 0; o >>= 1)
            s += __shfl_xor_sync(0xffffffffu, s, o);
        float inv = 1.0f / fmaxf(sqrtf(s), 1e-12f);
        acc[0] += a.x*inv; acc[1] += a.y*inv; acc[2] += a.z*inv; acc[3] += a.w*inv;
        acc[4] += b.x*inv; acc[5] += b.y*inv; acc[6] += b.z*inv; acc[7] += b.w*inv;
        r += stride;
    }

    // combine 4 warps' partials: warp w's lane l owns cols [8l, 8l+8)
    __shared__ float sacc[4][FEAT];
    __shared__ int   role_sh;
    #pragma unroll
    for (int j = 0; j < 8; ++j) sacc[warp][lane * 8 + j] = acc[j];
    __syncthreads();

    float sum0 = sacc[0][tid]       + sacc[1][tid]       + sacc[2][tid]       + sacc[3][tid];
    float sum1 = sacc[0][tid + 128] + sacc[1][tid + 128] + sacc[2][tid + 128] + sacc[3][tid + 128];

    int   step     = step_ptr ? __ldg(step_ptr) : 5000;
    float progress = fminf(1.0f, (float)step / 2000.0f);   // WARMUP_STEPS*10
    float m        = 0.99f + (0.999f - 0.99f) * progress;

    bool present = (count > 0);
    bool inited  = (__ldg(&init_mask[c]) > 0);
    float rcount = 1.0f / fmaxf((float)count, 1.0f);

    if (!split) {
        // barrier above guarantees all threads consumed `count`
        if (tid == 0) g_cursor_pad[c * CPAD] = 0;
        #pragma unroll
        for (int h = 0; h < 2; ++h) {
            int col  = tid + h * 128;
            float mean  = (h == 0 ? sum0 : sum1) * rcount;
            float proto = __ldg(&prototypes[(size_t)c * FEAT + col]);
            float np;
            if (present && inited) np = m * proto + (1.0f - m) * mean;
            else if (present)      np = mean;
            else                   np = proto;
            out[OUT_PROTO + (size_t)c * FEAT + col] = np;
        }
        if (tid == 0)
            out[OUT_INIT + c] = (inited || present) ? 1.0f : 0.0f;
        return;
    }

    // ---- split-class merge: both halves add partials; 2nd finisher wins ----
    atomicAdd(&g_partial[sidx * FEAT + tid],       sum0);
    atomicAdd(&g_partial[sidx * FEAT + tid + 128], sum1);
    __threadfence();            // release partials before the flag
    __syncthreads();
    if (tid == 0) role_sh = atomicAdd(&g_flag[sidx], 1);
    __syncthreads();

    if (role_sh == 1) {         // this CTA finished second -> finalize
        __threadfence();        // acquire the other half's partials
        #pragma unroll
        for (int h = 0; h < 2; ++h) {
            int col = tid + h * 128;
            float sum   = g_partial[sidx * FEAT + col];
            float mean  = sum * rcount;
            float proto = __ldg(&prototypes[(size_t)c * FEAT + col]);
            float np;
            if (present && inited) np = m * proto + (1.0f - m) * mean;
            else if (present)      np = mean;
            else                   np = proto;
            out[OUT_PROTO + (size_t)c * FEAT + col] = np;
            g_partial[sidx * FEAT + col] = 0.f;   // restore invariant
        }
        if (tid == 0) {
            out[OUT_INIT + c] = (inited || present) ? 1.0f : 0.0f;
            g_flag[sidx]          = 0;            // restore invariant
            g_cursor_pad[c * CPAD] = 0;           // both halves read it already
        }
    }
}

// ---------------- launch ------------------------------------------------
extern "C" void kernel_launch(void* const* d_in, const int* in_sizes, int n_in,
                              void* d_out, int out_size)
{
    const float* features   = (const float*)d_in[0];
    const int*   labels     = (const int*)  d_in[1];
    const int*   lpi        = (const int*)  d_in[2];
    const float* prototypes = (const float*)d_in[3];
    const int*   init_mask  = (const int*)  d_in[4];
    const float* cooc_in    = (const float*)d_in[5];
    const int*   step_ptr   = (n_in >= 7) ? (const int*)d_in[6] : nullptr;
    float*       out        = (float*)d_out;

    k_cooc_scatter<<<K1_GRID, 256>>>(labels, lpi, cooc_in, out);
    k_class_accum<<<ACC_GRID, 128>>>(features, prototypes, init_mask, step_ptr, out);
}